// round 3
// baseline (speedup 1.0000x reference)
#include <cuda_runtime.h>
#include <math.h>
#include <string.h>

// GaussianBlurDM single-pass rewrite.
//
// Key identity: jnp.pad(mode='reflect') + VALID conv == convolution against the
// whole-sample symmetric extension. All such operators (symmetric kernel) share
// the DCT-I eigenbasis cos(pi*m*n/255), so B^t == reflect-conv with the t-fold
// self-convolution of the base kernel (half-width 5t <= 95 <= 255 => exact).
// We truncate that composed kernel where tail mass < 1e-6 (r <= 44).
//
// => out[b] = H-conv(V-conv(x[b], K_{t[b]}), K_{t[b]})  -- just TWO kernels.

#define BATCH 64
#define CHAN 3
#define IMG 256
#define IMG_PIX (IMG * IMG)
#define NT 19
#define RMAX 44
#define KLEN 96           // holds 2*RMAX+1 = 89 weights (full symmetric array)

struct BlurParams {
    float K[NT][KLEN];    // K[t-1][jj] = composed kernel weight at offset jj-r
    int   r[NT];          // truncation radius per t
};

__device__ float g_mid[BATCH * CHAN * IMG_PIX];   // ~50 MB scratch

__device__ __forceinline__ int reflect256(int v) {
    v = (v < 0) ? -v : v;
    return (v > 255) ? (510 - v) : v;
}

// 8 FMAs sharing one weight (ring registers hold 8 consecutive input samples)
#define STEP8(W, x0,x1,x2,x3,x4,x5,x6,x7) \
    a0 = fmaf(W, x0, a0); a1 = fmaf(W, x1, a1); \
    a2 = fmaf(W, x2, a2); a3 = fmaf(W, x3, a3); \
    a4 = fmaf(W, x4, a4); a5 = fmaf(W, x5, a5); \
    a6 = fmaf(W, x6, a6); a7 = fmaf(W, x7, a7);

// ---------------------------------------------------------------------------
// Vertical pass: CTA = 64 rows x 256 cols. Thread = one column.
// smem tile holds rows [R0-r, R0+63+r+8] (Q = 2r+65 rows, stride 256 floats).
// ---------------------------------------------------------------------------
__global__ void __launch_bounds__(256) blur_v(
    const float* __restrict__ x, float* __restrict__ mid,
    const int* __restrict__ t, BlurParams P)
{
    extern __shared__ float s[];
    const int col = threadIdx.x;
    const int R0 = blockIdx.x * 64;
    const int bc = blockIdx.z * CHAN + blockIdx.y;
    const float* img = x + ((long)bc << 16);
    float* dst = mid + ((long)bc << 16);

    int tb = t[blockIdx.z];
    if (tb <= 0) {   // identity (t<=0 never blurred)
        for (int i = 0; i < 64; ++i)
            dst[((R0 + i) << 8) + col] = img[((R0 + i) << 8) + col];
        return;
    }
    const int ti = min(tb, NT) - 1;
    const int r = P.r[ti];
    const float* __restrict__ Kt = P.K[ti];
    const int Q = 2 * r + 65;

    // Vectorized fill: 4 rows per iteration (64 lanes of float4 per row).
    {
        const float4* img4 = (const float4*)img;
        float4* s4 = (float4*)s;
        const int lane = col & 63;
        for (int q = (col >> 6); q < Q; q += 4) {
            int g = reflect256(R0 - r + q);
            s4[(q << 6) + lane] = img4[(g << 6) + lane];
        }
    }
    __syncthreads();

    const int nd = 2 * r + 1;
    #pragma unroll 1
    for (int grp = 0; grp < 8; ++grp) {
        const float* sp = s + ((grp * 8) << 8) + col;   // sp[q<<8] = row sb+q
        float a0 = 0.f, a1 = 0.f, a2 = 0.f, a3 = 0.f;
        float a4 = 0.f, a5 = 0.f, a6 = 0.f, a7 = 0.f;
        float v0 = sp[0 << 8], v1 = sp[1 << 8], v2 = sp[2 << 8], v3 = sp[3 << 8];
        float v4 = sp[4 << 8], v5 = sp[5 << 8], v6 = sp[6 << 8], v7 = sp[7 << 8];
        int jj = 0;
        for (; jj + 8 <= nd; jj += 8) {
            STEP8(Kt[jj + 0], v0, v1, v2, v3, v4, v5, v6, v7); v0 = sp[(jj + 8)  << 8];
            STEP8(Kt[jj + 1], v1, v2, v3, v4, v5, v6, v7, v0); v1 = sp[(jj + 9)  << 8];
            STEP8(Kt[jj + 2], v2, v3, v4, v5, v6, v7, v0, v1); v2 = sp[(jj + 10) << 8];
            STEP8(Kt[jj + 3], v3, v4, v5, v6, v7, v0, v1, v2); v3 = sp[(jj + 11) << 8];
            STEP8(Kt[jj + 4], v4, v5, v6, v7, v0, v1, v2, v3); v4 = sp[(jj + 12) << 8];
            STEP8(Kt[jj + 5], v5, v6, v7, v0, v1, v2, v3, v4); v5 = sp[(jj + 13) << 8];
            STEP8(Kt[jj + 6], v6, v7, v0, v1, v2, v3, v4, v5); v6 = sp[(jj + 14) << 8];
            STEP8(Kt[jj + 7], v7, v0, v1, v2, v3, v4, v5, v6); v7 = sp[(jj + 15) << 8];
        }
        for (; jj < nd; ++jj) {   // <=7 leftover taps: direct smem reads
            float w = Kt[jj];
            a0 = fmaf(w, sp[(jj + 0) << 8], a0); a1 = fmaf(w, sp[(jj + 1) << 8], a1);
            a2 = fmaf(w, sp[(jj + 2) << 8], a2); a3 = fmaf(w, sp[(jj + 3) << 8], a3);
            a4 = fmaf(w, sp[(jj + 4) << 8], a4); a5 = fmaf(w, sp[(jj + 5) << 8], a5);
            a6 = fmaf(w, sp[(jj + 6) << 8], a6); a7 = fmaf(w, sp[(jj + 7) << 8], a7);
        }
        float* dp = dst + ((R0 + grp * 8) << 8) + col;
        dp[0 << 8] = a0; dp[1 << 8] = a1; dp[2 << 8] = a2; dp[3 << 8] = a3;
        dp[4 << 8] = a4; dp[5 << 8] = a5; dp[6 << 8] = a6; dp[7 << 8] = a7;
    }
}

// ---------------------------------------------------------------------------
// Horizontal pass: CTA = 128 rows x 256 cols, full rows in smem (stride 257
// keeps lane-per-row accesses conflict-free). Thread = (row = tid&127,
// column half = tid>>7); 16 groups of 8 output columns per thread; reflect
// indices are warp-uniform. Stores are 2x float4 (one 32B sector each).
// ---------------------------------------------------------------------------
#define HSTRIDE 257

__global__ void __launch_bounds__(256) blur_h(
    const float* __restrict__ mid, float* __restrict__ out,
    const int* __restrict__ t, BlurParams P)
{
    extern __shared__ float s[];
    const int tid = threadIdx.x;
    const int R0 = blockIdx.x * 128;
    const int bc = blockIdx.z * CHAN + blockIdx.y;
    const float* img = mid + ((long)bc << 16) + ((long)R0 << 8);
    float* dst = out + ((long)bc << 16) + ((long)R0 << 8);

    int tb = t[blockIdx.z];
    if (tb <= 0) {
        for (int i = tid; i < 128 * IMG; i += 256) dst[i] = img[i];
        return;
    }
    const int ti = min(tb, NT) - 1;
    const int r = P.r[ti];
    const float* __restrict__ Kt = P.K[ti];

    // Fill: float4 global loads, scalar smem stores (odd stride).
    {
        const float4* img4 = (const float4*)img;
        for (int i = tid; i < 128 * 64; i += 256) {
            int row = i >> 6, c4 = i & 63;
            float4 v = img4[i];
            float* sp = s + row * HSTRIDE + (c4 << 2);
            sp[0] = v.x; sp[1] = v.y; sp[2] = v.z; sp[3] = v.w;
        }
    }
    __syncthreads();

    const int row = tid & 127;
    const int half = tid >> 7;
    const float* __restrict__ srow = s + row * HSTRIDE;
    const int nd = 2 * r + 1;

    #pragma unroll 1
    for (int grp = 0; grp < 16; ++grp) {
        const int c0 = (half << 7) + (grp << 3);
        const int cb0 = c0 - r;
        float a0 = 0.f, a1 = 0.f, a2 = 0.f, a3 = 0.f;
        float a4 = 0.f, a5 = 0.f, a6 = 0.f, a7 = 0.f;
        float v0 = srow[reflect256(cb0 + 0)], v1 = srow[reflect256(cb0 + 1)];
        float v2 = srow[reflect256(cb0 + 2)], v3 = srow[reflect256(cb0 + 3)];
        float v4 = srow[reflect256(cb0 + 4)], v5 = srow[reflect256(cb0 + 5)];
        float v6 = srow[reflect256(cb0 + 6)], v7 = srow[reflect256(cb0 + 7)];
        int jj = 0;
        for (; jj + 8 <= nd; jj += 8) {
            const int cb = cb0 + jj;
            STEP8(Kt[jj + 0], v0, v1, v2, v3, v4, v5, v6, v7); v0 = srow[reflect256(cb + 8)];
            STEP8(Kt[jj + 1], v1, v2, v3, v4, v5, v6, v7, v0); v1 = srow[reflect256(cb + 9)];
            STEP8(Kt[jj + 2], v2, v3, v4, v5, v6, v7, v0, v1); v2 = srow[reflect256(cb + 10)];
            STEP8(Kt[jj + 3], v3, v4, v5, v6, v7, v0, v1, v2); v3 = srow[reflect256(cb + 11)];
            STEP8(Kt[jj + 4], v4, v5, v6, v7, v0, v1, v2, v3); v4 = srow[reflect256(cb + 12)];
            STEP8(Kt[jj + 5], v5, v6, v7, v0, v1, v2, v3, v4); v5 = srow[reflect256(cb + 13)];
            STEP8(Kt[jj + 6], v6, v7, v0, v1, v2, v3, v4, v5); v6 = srow[reflect256(cb + 14)];
            STEP8(Kt[jj + 7], v7, v0, v1, v2, v3, v4, v5, v6); v7 = srow[reflect256(cb + 15)];
        }
        for (; jj < nd; ++jj) {
            float w = Kt[jj];
            const int cb = cb0 + jj;
            a0 = fmaf(w, srow[reflect256(cb + 0)], a0); a1 = fmaf(w, srow[reflect256(cb + 1)], a1);
            a2 = fmaf(w, srow[reflect256(cb + 2)], a2); a3 = fmaf(w, srow[reflect256(cb + 3)], a3);
            a4 = fmaf(w, srow[reflect256(cb + 4)], a4); a5 = fmaf(w, srow[reflect256(cb + 5)], a5);
            a6 = fmaf(w, srow[reflect256(cb + 6)], a6); a7 = fmaf(w, srow[reflect256(cb + 7)], a7);
        }
        float4 lo = make_float4(a0, a1, a2, a3);
        float4 hi = make_float4(a4, a5, a6, a7);
        float* dp = dst + (row << 8) + c0;
        *(float4*)(dp + 0) = lo;
        *(float4*)(dp + 4) = hi;
    }
}

// ---------------------------------------------------------------------------
extern "C" void kernel_launch(void* const* d_in, const int* in_sizes, int n_in,
                              void* d_out, int out_size) {
    const float* x = (const float*)d_in[0];
    const int* t = (const int*)d_in[1];
    float* out = (float*)d_out;

    // ---- Host: base kernel (match reference: f32-rounded weights), then
    //      t-fold self-convolutions in double, truncated at tail mass 1e-6.
    BlurParams P;
    memset(&P, 0, sizeof(P));
    {
        double pdf[11], sum = 0.0;
        for (int i = 0; i < 11; ++i) {
            double xi = -5.0 + (double)i;
            pdf[i] = exp(-0.5 * (xi / 2.0) * (xi / 2.0));
            sum += pdf[i];
        }
        double base[11];
        for (int i = 0; i < 11; ++i)
            base[i] = (double)((float)(pdf[i] / sum));   // f32-rounded like _k1d

        double f[200];
        for (int i = 0; i < 11; ++i) f[i] = base[i];
        int hw = 5;                                      // f length = 2*hw+1

        for (int tt = 1; tt <= NT; ++tt) {
            // pick truncation radius: smallest r with 2*tail(r+1) <= 1e-6
            double acc = 0.0;
            int r = 0;
            for (int a = hw; a >= 1; --a) {
                acc += f[hw + a];
                if (2.0 * acc > 1e-6) { r = a; break; }
            }
            if (r > RMAX) r = RMAX;
            P.r[tt - 1] = r;
            for (int jj = 0; jj <= 2 * r; ++jj)
                P.K[tt - 1][jj] = (float)f[hw + (jj - r)];

            if (tt < NT) {   // f = f (*) base
                int L = 2 * hw + 1;
                double g[200];
                for (int i = 0; i < L + 10; ++i) g[i] = 0.0;
                for (int n = 0; n < L; ++n) {
                    double fn = f[n];
                    for (int k = 0; k < 11; ++k) g[n + k] += fn * base[k];
                }
                for (int i = 0; i < L + 10; ++i) f[i] = g[i];
                hw += 5;
            }
        }
    }

    float* mid;
    cudaGetSymbolAddress((void**)&mid, g_mid);

    const int V_SMEM = (2 * RMAX + 65) * IMG * (int)sizeof(float);   // 156672
    const int H_SMEM = 128 * HSTRIDE * (int)sizeof(float);           // 131584
    cudaFuncSetAttribute(blur_v, cudaFuncAttributeMaxDynamicSharedMemorySize, V_SMEM);
    cudaFuncSetAttribute(blur_h, cudaFuncAttributeMaxDynamicSharedMemorySize, H_SMEM);

    dim3 block(256);
    dim3 gv(IMG / 64, CHAN, BATCH);    // 4 x 3 x 64
    dim3 gh(IMG / 128, CHAN, BATCH);   // 2 x 3 x 64
    blur_v<<<gv, block, V_SMEM>>>(x, mid, t, P);
    blur_h<<<gh, block, H_SMEM>>>(mid, out, t, P);
}

// round 4
// speedup vs baseline: 1.9639x; 1.9639x over previous
#include <cuda_runtime.h>
#include <math.h>
#include <string.h>

// GaussianBlurDM, round 3.
//
// out[b] = reflect-conv(reflect-conv(x[b], K_t, axis=H), K_t, axis=W) where
// K_t = t-fold self-convolution of the base 11-tap Gaussian (exact identity,
// DCT-I eigenbasis of whole-sample-symmetric extension), truncated at tail
// mass 5e-5.
//
// Both passes run the SAME kernel: a vertical reflect-convolution that writes
// its output transposed. Pass1: x[h][w] -> mid[w][h]. Pass2: mid[w][h] ->
// out[h][w]. Each thread owns 2 adjacent columns (packed f32x2 via
// fma.rn.f32x2) and 16 output rows (ring registers). No shared memory.

#define BATCH 64
#define CHAN 3
#define IMG 256
#define NT 19
#define KLEN 96
#define NSLOT (NT + 1)   // slot NT = identity (safety for t<=0)

typedef unsigned long long u64;

struct BlurParams {
    float2 K[NSLOT][KLEN];  // weight duplicated into both lanes; zero-padded
    int r[NSLOT];           // truncation radius
    int ndp[NSLOT];         // tap count padded to multiple of 16
};

__device__ float g_mid[BATCH * CHAN * IMG * IMG];   // ~50 MB transposed scratch

__device__ __forceinline__ int reflect256(int v) {
    v = abs(v);
    return (v > 255) ? (510 - v) : v;
}

__device__ __forceinline__ u64 ffma2(u64 a, u64 b, u64 c) {
    u64 d;
    asm("fma.rn.f32x2 %0, %1, %2, %3;" : "=l"(d) : "l"(a), "l"(b), "l"(c));
    return d;
}

// CTA: 128 threads (one per column pair), 16 output rows. Grid: (16, C, B).
__global__ void __launch_bounds__(128) conv_pass(
    const float* __restrict__ src, float* __restrict__ dst,
    const int* __restrict__ t, const __grid_constant__ BlurParams P)
{
    const int tid = threadIdx.x;
    const int m0 = blockIdx.x << 4;                    // first output row
    const int bc = blockIdx.z * CHAN + blockIdx.y;
    const u64* __restrict__ scol =
        (const u64*)(src + ((long)bc << 16)) + tid;    // row stride = 128 u64
    float* dimg = dst + ((long)bc << 16);

    const int tb = t[blockIdx.z];
    const int ti = (tb >= 1) ? ((tb > NT) ? (NT - 1) : (tb - 1)) : NT;
    const float2* __restrict__ Kt = P.K[ti];
    const int r = P.r[ti];
    const int ndp = P.ndp[ti];
    const int gbase = m0 - r;

    u64 acc[16], ring[16];
    #pragma unroll
    for (int k = 0; k < 16; ++k) acc[k] = 0ull;
    #pragma unroll
    for (int k = 0; k < 16; ++k)
        ring[k] = __ldg(scol + (reflect256(gbase + k) << 7));

    #pragma unroll 1
    for (int jj = 0; jj < ndp; jj += 16) {
        #pragma unroll
        for (int u = 0; u < 16; ++u) {
            float2 wf = Kt[jj + u];          // uniform -> constant-bank load
            u64 w;
            asm("mov.b64 %0, {%1, %2};" : "=l"(w) : "f"(wf.x), "f"(wf.y));
            #pragma unroll
            for (int k = 0; k < 16; ++k)
                acc[k] = ffma2(ring[(u + k) & 15], w, acc[k]);
            // refill slot u with row gbase + jj + 16 + u (reflect keeps it
            // in-bounds even for the zero-weight padding overrun)
            ring[u] = __ldg(scol + (reflect256(gbase + jj + 16 + u) << 7));
        }
    }

    // Transposed store: column c writes dst[c][m0..m0+15] (64 B contiguous).
    const int c0 = tid << 1;
    float lo[16], hi[16];
    #pragma unroll
    for (int k = 0; k < 16; ++k) {
        float ax, ay;
        asm("mov.b64 {%0, %1}, %2;" : "=f"(ax), "=f"(ay) : "l"(acc[k]));
        lo[k] = ax; hi[k] = ay;
    }
    float4* d0 = (float4*)(dimg + c0 * IMG + m0);
    float4* d1 = (float4*)(dimg + (c0 + 1) * IMG + m0);
    #pragma unroll
    for (int q = 0; q < 4; ++q) {
        d0[q] = make_float4(lo[4 * q], lo[4 * q + 1], lo[4 * q + 2], lo[4 * q + 3]);
        d1[q] = make_float4(hi[4 * q], hi[4 * q + 1], hi[4 * q + 2], hi[4 * q + 3]);
    }
}

// ---------------------------------------------------------------------------
extern "C" void kernel_launch(void* const* d_in, const int* in_sizes, int n_in,
                              void* d_out, int out_size) {
    const float* x = (const float*)d_in[0];
    const int* t = (const int*)d_in[1];
    float* out = (float*)d_out;

    static BlurParams P;                 // host-side; passed by value
    memset(&P, 0, sizeof(P));
    {
        // Base kernel, f32-rounded exactly like the reference's _k1d.
        double pdf[11], sum = 0.0;
        for (int i = 0; i < 11; ++i) {
            double xi = -5.0 + (double)i;
            pdf[i] = exp(-0.5 * (xi / 2.0) * (xi / 2.0));
            sum += pdf[i];
        }
        double base[11];
        for (int i = 0; i < 11; ++i)
            base[i] = (double)((float)(pdf[i] / sum));

        double f[220];
        for (int i = 0; i < 220; ++i) f[i] = 0.0;
        for (int i = 0; i < 11; ++i) f[i] = base[i];
        int hw = 5;

        const double TAIL = 5e-5;
        for (int tt = 1; tt <= NT; ++tt) {
            double acc = 0.0;
            int r = 0;
            for (int a = hw; a >= 1; --a) {
                acc += f[hw + a];
                if (2.0 * acc > TAIL) { r = a; break; }
            }
            int nd = 2 * r + 1;
            int ndp = (nd + 15) & ~15;
            if (ndp > KLEN) ndp = KLEN;
            P.r[tt - 1] = r;
            P.ndp[tt - 1] = ndp;
            for (int jj = 0; jj < nd && jj < KLEN; ++jj) {
                float w = (float)f[hw + (jj - r)];
                P.K[tt - 1][jj].x = w;
                P.K[tt - 1][jj].y = w;
            }
            if (tt < NT) {   // f = f (*) base
                int L = 2 * hw + 1;
                double g[220];
                for (int i = 0; i < 220; ++i) g[i] = 0.0;
                for (int n = 0; n < L; ++n) {
                    double fn = f[n];
                    for (int k = 0; k < 11; ++k) g[n + k] += fn * base[k];
                }
                for (int i = 0; i < 220; ++i) f[i] = g[i];
                hw += 5;
            }
        }
        // Identity slot (t <= 0 safety): single unit tap -> bit-exact copy.
        P.r[NT] = 0;
        P.ndp[NT] = 16;
        P.K[NT][0].x = 1.0f;
        P.K[NT][0].y = 1.0f;
    }

    float* mid;
    cudaGetSymbolAddress((void**)&mid, g_mid);

    dim3 block(128);
    dim3 grid(IMG / 16, CHAN, BATCH);   // 16 x 3 x 64 = 3072 CTAs
    conv_pass<<<grid, block>>>(x, mid, t, P);   // x[h][w]   -> mid[w][h]
    conv_pass<<<grid, block>>>(mid, out, t, P); // mid[w][h] -> out[h][w]
}